// round 4
// baseline (speedup 1.0000x reference)
#include <cuda_runtime.h>
#include <math.h>

#define T 1024
#define B 32
#define INPUT_DIM 256
#define H 512
#define H3 1536
#define FEAT (2*H)

#define NCTAS_DIR 32          // CTAs per direction
#define ROWS_CTA 16           // hidden rows per CTA (48 gate rows)

// ---- device scratch ----
__device__ __align__(256) float g_xT[T * INPUT_DIM * B];              // tf32 bits
__device__ __align__(256) float g_Xi[2u * T * H3 * B];                // fp32
__device__ __align__(256) float g_yA[T * FEAT * B];                   // tf32 bits
__device__ __align__(256) float g_yB[T * FEAT * B];                   // tf32 bits
__device__ __align__(256) float g_htf[2][2][H][B];                    // tf32 bits, dbl-buffered
__device__ unsigned long long g_cnt2[2];
__device__ unsigned long long g_rel2[2];

// ---------------- helpers ----------------------------------------------------
__device__ __forceinline__ unsigned cvt_tf32(float f) {
    unsigned r;
    asm("cvt.rna.tf32.f32 %0, %1;" : "=r"(r) : "f"(f));
    return r;
}

__device__ __forceinline__ void mma8(float* d, const unsigned* a,
                                     unsigned b0, unsigned b1) {
    asm("mma.sync.aligned.m16n8k8.row.col.f32.tf32.tf32.f32 "
        "{%0,%1,%2,%3},{%4,%5,%6,%7},{%8,%9},{%0,%1,%2,%3};"
        : "+f"(d[0]), "+f"(d[1]), "+f"(d[2]), "+f"(d[3])
        : "r"(a[0]), "r"(a[1]), "r"(a[2]), "r"(a[3]), "r"(b0), "r"(b1));
}

// per-direction grid barrier (monotonic ticket; replay-safe)
__device__ __forceinline__ void dir_sync(int dir) {
    __syncthreads();
    if (threadIdx.x == 0) {
        __threadfence();
        unsigned long long a = atomicAdd(&g_cnt2[dir], 1ull) + 1ull;
        unsigned long long goal = ((a + NCTAS_DIR - 1) / NCTAS_DIR) * NCTAS_DIR;
        if (a == goal) {
            atomicMax(&g_rel2[dir], goal);
        } else {
            while (*((volatile unsigned long long*)&g_rel2[dir]) < goal) { }
        }
        __threadfence();
    }
    __syncthreads();
}

// ---------------- transpose + tf32 round: x[t][b][k] -> g_xT[t][k][b] --------
__global__ void transpose_x(const float* __restrict__ x) {
    __shared__ float sm[B][INPUT_DIM + 1];
    int t = blockIdx.x;
    const float* xin = x + (size_t)t * B * INPUT_DIM;
    for (int i = threadIdx.x; i < B * INPUT_DIM; i += 256) {
        int b = i >> 8, k = i & 255;
        sm[b][k] = xin[i];
    }
    __syncthreads();
    float* xo = g_xT + (size_t)t * INPUT_DIM * B;
    for (int i = threadIdx.x; i < B * INPUT_DIM; i += 256) {
        int k = i >> 5, b = i & 31;
        xo[i] = __uint_as_float(cvt_tf32(sm[b][k]));
    }
}

// ---------------- Xi GEMM (tf32 tensor cores) -------------------------------
__global__ __launch_bounds__(256) void gemm_xi(const float* __restrict__ A,
                                               const float* __restrict__ Wih,
                                               const float* __restrict__ bih,
                                               int K) {
    __shared__ float Ws[128 * 36];
    __shared__ float xs[4 * 32 * 40];

    int t0  = blockIdx.x * 4;
    int dir = blockIdx.y / 12;
    int g0  = (blockIdx.y % 12) * 128;
    int tid = threadIdx.x;
    int l   = tid & 31;
    int w   = tid >> 5;
    int wm  = w & 3;
    int wn  = w >> 2;

    const float* Wp = Wih + ((size_t)dir * H3 + g0) * (size_t)K;

    float acc[2][8][4];
#pragma unroll
    for (int mt = 0; mt < 2; mt++)
#pragma unroll
        for (int q = 0; q < 8; q++)
#pragma unroll
            for (int s = 0; s < 4; s++) acc[mt][q][s] = 0.f;

    for (int k0 = 0; k0 < K; k0 += 32) {
#pragma unroll
        for (int i = 0; i < 4; i++) {
            int fid = tid + i * 256;
            int g = fid >> 3, kq = fid & 7;
            float4 wv = *(const float4*)&Wp[(size_t)g * K + k0 + kq * 4];
            float4 o;
            o.x = __uint_as_float(cvt_tf32(wv.x));
            o.y = __uint_as_float(cvt_tf32(wv.y));
            o.z = __uint_as_float(cvt_tf32(wv.z));
            o.w = __uint_as_float(cvt_tf32(wv.w));
            *(float4*)&Ws[g * 36 + kq * 4] = o;
        }
#pragma unroll
        for (int i = 0; i < 4; i++) {
            int fid = tid + i * 256;
            int tp = fid >> 8, k = (fid >> 3) & 31, bq = fid & 7;
            float4 xv = *(const float4*)&A[((size_t)(t0 + tp) * K + k0 + k) * B + bq * 4];
            *(float4*)&xs[tp * 1280 + k * 40 + bq * 4] = xv;
        }
        __syncthreads();

#pragma unroll
        for (int ki = 0; ki < 4; ki++) {
            unsigned a[2][4];
#pragma unroll
            for (int mt = 0; mt < 2; mt++) {
                int row = wm * 32 + mt * 16 + (l >> 2);
                int kk = ki * 8 + (l & 3);
                a[mt][0] = __float_as_uint(Ws[row * 36 + kk]);
                a[mt][1] = __float_as_uint(Ws[(row + 8) * 36 + kk]);
                a[mt][2] = __float_as_uint(Ws[row * 36 + kk + 4]);
                a[mt][3] = __float_as_uint(Ws[(row + 8) * 36 + kk + 4]);
            }
#pragma unroll
            for (int q = 0; q < 8; q++) {
                int n = wn * 64 + q * 8;
                int tp = n >> 5, bb = (n & 31) + (l >> 2);
                int kk = ki * 8 + (l & 3);
                unsigned b0 = __float_as_uint(xs[tp * 1280 + kk * 40 + bb]);
                unsigned b1 = __float_as_uint(xs[tp * 1280 + (kk + 4) * 40 + bb]);
                mma8(acc[0][q], a[0], b0, b1);
                mma8(acc[1][q], a[1], b0, b1);
            }
        }
        __syncthreads();
    }

    float bias[2][2];
#pragma unroll
    for (int mt = 0; mt < 2; mt++) {
        int r = g0 + wm * 32 + mt * 16 + (l >> 2);
        bias[mt][0] = bih[dir * H3 + r];
        bias[mt][1] = bih[dir * H3 + r + 8];
    }
#pragma unroll
    for (int mt = 0; mt < 2; mt++)
#pragma unroll
        for (int q = 0; q < 8; q++) {
            int n = wn * 64 + q * 8;
            int tp = n >> 5;
            int bb = (n & 31) + (l & 3) * 2;
            int r = g0 + wm * 32 + mt * 16 + (l >> 2);
            size_t base = (size_t)(dir * T + t0 + tp) * H3;
            float2 v0 = make_float2(acc[mt][q][0] + bias[mt][0],
                                    acc[mt][q][1] + bias[mt][0]);
            float2 v1 = make_float2(acc[mt][q][2] + bias[mt][1],
                                    acc[mt][q][3] + bias[mt][1]);
            *(float2*)&g_Xi[(base + r) * B + bb] = v0;
            *(float2*)&g_Xi[(base + r + 8) * B + bb] = v1;
        }
}

// ---------------- persistent recurrence ------------------------------------
// 64 CTAs: dir = cta>>5, J0 = (cta&31)*16 -> 48 gate rows = 3 m16 tiles (r,z,n).
// Warp ws owns k-slice [ws*64, +64); W_hh A-fragments live in registers.
// Hst: warp-private smem [64][40]; Ps: [8][48][32] partials.
#define HST_W 2560                       // floats per warp (64*40)
#define HST_F (8 * HST_W)                // 20480 floats
#define PS_F (8 * 48 * 32)               // 12288 floats
#define SMEM_REC ((HST_F + PS_F + 64) * 4)

__global__ __launch_bounds__(256, 1) void gru_rec(const float* __restrict__ whh,
                                                  const float* __restrict__ bhh,
                                                  float* __restrict__ y,
                                                  float* __restrict__ out,
                                                  int layer) {
    extern __shared__ float smem[];
    float* Hst = smem;                   // warp-private staging
    float* Ps  = smem + HST_F;
    float* bias_s = smem + HST_F + PS_F;

    int cta = blockIdx.x;
    int dir = cta >> 5;
    int J0  = (cta & 31) * ROWS_CTA;
    int tid = threadIdx.x;
    int l   = tid & 31;
    int ws  = tid >> 5;
    int jj2 = tid >> 5;      // epilogue: rows jj2, jj2+8
    int b   = tid & 31;

    // preload W_hh A-fragments (3 m-tiles x 8 k-tiles), tf32
    unsigned afr[3][8][4];
    {
        const float* wp = whh + (size_t)dir * H3 * H;
#pragma unroll
        for (int mt = 0; mt < 3; mt++)
#pragma unroll
            for (int ki = 0; ki < 8; ki++)
#pragma unroll
                for (int s = 0; s < 4; s++) {
                    int jj = (l >> 2) + (s & 1) * 8;
                    int k  = ws * 64 + ki * 8 + (l & 3) + (s >> 1) * 4;
                    afr[mt][ki][s] =
                        cvt_tf32(wp[(size_t)(mt * H + J0 + jj) * H + k]);
                }
    }
    if (tid < 48)
        bias_s[tid] = bhh[dir * H3 + (tid >> 4) * H + J0 + (tid & 15)];

    // init h = 0 (buffer 0, our 16 rows) + register hold
    float hold[2] = {0.f, 0.f};
    g_htf[0][dir][J0 + jj2][b] = 0.f;
    g_htf[0][dir][J0 + jj2 + 8][b] = 0.f;
    __threadfence();
    dir_sync(dir);

    float* HstW = Hst + ws * HST_W;
    const float4* hbase[2] = {(const float4*)&g_htf[0][dir][0][0],
                              (const float4*)&g_htf[1][dir][0][0]};

    // prefetch Xi for step 0
    float xi[2][3];
    {
        int t = dir ? (T - 1) : 0;
#pragma unroll
        for (int p = 0; p < 2; p++) {
            const float* xip = g_Xi +
                (((size_t)dir * T + t) * H3 + J0 + jj2 + p * 8) * B + b;
            xi[p][0] = __ldg(xip);
            xi[p][1] = __ldg(xip + (size_t)H * B);
            xi[p][2] = __ldg(xip + (size_t)2 * H * B);
        }
    }

    for (int step = 0; step < T; step++) {
        int t   = dir ? (T - 1 - step) : step;
        int cur = step & 1, nxt = cur ^ 1;

        // stage own k-slice of h (tf32 bits), warp-local
        const float4* hp = hbase[cur];
#pragma unroll
        for (int i = 0; i < 16; i++) {
            int kl = i * 4 + (l >> 3);          // 0..63
            int b4 = l & 7;
            float4 v = __ldcg(hp + (size_t)(ws * 64 + kl) * 8 + b4);
            *(float4*)&HstW[kl * 40 + b4 * 4] = v;
        }
        __syncwarp();

        // mma: 48 x 32 x 64 per warp
        float acc[3][4][4];
#pragma unroll
        for (int mt = 0; mt < 3; mt++)
#pragma unroll
            for (int q = 0; q < 4; q++)
#pragma unroll
                for (int s = 0; s < 4; s++) acc[mt][q][s] = 0.f;

#pragma unroll
        for (int ki = 0; ki < 8; ki++) {
            int kk = ki * 8 + (l & 3);
#pragma unroll
            for (int q = 0; q < 4; q++) {
                int bb = q * 8 + (l >> 2);
                unsigned b0 = __float_as_uint(HstW[kk * 40 + bb]);
                unsigned b1 = __float_as_uint(HstW[(kk + 4) * 40 + bb]);
                mma8(acc[0][q], afr[0][ki], b0, b1);
                mma8(acc[1][q], afr[1][ki], b0, b1);
                mma8(acc[2][q], afr[2][ki], b0, b1);
            }
        }

        // partials
#pragma unroll
        for (int mt = 0; mt < 3; mt++)
#pragma unroll
            for (int q = 0; q < 4; q++) {
                int row = mt * 16 + (l >> 2);
                int col = q * 8 + (l & 3) * 2;
                *(float2*)&Ps[ws * 1536 + row * 32 + col] =
                    make_float2(acc[mt][q][0], acc[mt][q][1]);
                *(float2*)&Ps[ws * 1536 + (row + 8) * 32 + col] =
                    make_float2(acc[mt][q][2], acc[mt][q][3]);
            }
        __syncthreads();

        // epilogue: rows jj2 and jj2+8
        float hnew[2];
#pragma unroll
        for (int p = 0; p < 2; p++) {
            int jr = jj2 + p * 8;
            float s0 = 0.f, s1 = 0.f, s2 = 0.f;
#pragma unroll
            for (int wq = 0; wq < 8; wq++) {
                s0 += Ps[wq * 1536 + jr * 32 + b];
                s1 += Ps[wq * 1536 + (16 + jr) * 32 + b];
                s2 += Ps[wq * 1536 + (32 + jr) * 32 + b];
            }
            float r = 1.f / (1.f + __expf(-(xi[p][0] + s0 + bias_s[jr])));
            float z = 1.f / (1.f + __expf(-(xi[p][1] + s1 + bias_s[16 + jr])));
            float n = tanhf(xi[p][2] + r * (s2 + bias_s[32 + jr]));
            hnew[p] = (1.f - z) * n + z * hold[p];
            hold[p] = hnew[p];

            float htf = __uint_as_float(cvt_tf32(hnew[p]));
            g_htf[nxt][dir][J0 + jr][b] = htf;
            y[((size_t)t * FEAT + dir * H + (J0 + jr)) * B + b] = htf;
            if (step == T - 1)
                out[(2 * layer + dir) * (B * H) + b * H + (J0 + jr)] = hnew[p];
        }
        __syncthreads();   // Ps consumed before next step's overwrite

        // prefetch Xi for next step (independent of barrier)
        if (step + 1 < T) {
            int tn = dir ? (T - 2 - step) : (step + 1);
#pragma unroll
            for (int p = 0; p < 2; p++) {
                const float* xip = g_Xi +
                    (((size_t)dir * T + tn) * H3 + J0 + jj2 + p * 8) * B + b;
                xi[p][0] = __ldg(xip);
                xi[p][1] = __ldg(xip + (size_t)H * B);
                xi[p][2] = __ldg(xip + (size_t)2 * H * B);
            }
        }

        dir_sync(dir);
    }
}

// ---------------- host launcher ---------------------------------------------
extern "C" void kernel_launch(void* const* d_in, const int* in_sizes, int n_in,
                              void* d_out, int out_size) {
    const float* x        = (const float*)d_in[0];
    const float* w_ih_l0  = (const float*)d_in[1];
    const float* w_hh_l0  = (const float*)d_in[2];
    const float* b_ih_l0  = (const float*)d_in[3];
    const float* b_hh_l0  = (const float*)d_in[4];
    const float* w_ih_lr  = (const float*)d_in[5];
    const float* w_hh_lr  = (const float*)d_in[6];
    const float* b_ih_lr  = (const float*)d_in[7];
    const float* b_hh_lr  = (const float*)d_in[8];
    float* out = (float*)d_out;

    cudaFuncSetAttribute(gru_rec, cudaFuncAttributeMaxDynamicSharedMemorySize,
                         SMEM_REC);

    void *pxT, *pyA, *pyB;
    cudaGetSymbolAddress(&pxT, g_xT);
    cudaGetSymbolAddress(&pyA, g_yA);
    cudaGetSymbolAddress(&pyB, g_yB);
    float* xT = (float*)pxT;
    float* yA = (float*)pyA;
    float* yB = (float*)pyB;

    dim3 ggrid(T / 4, 24);

    // layer 0
    transpose_x<<<T, 256>>>(x);
    gemm_xi<<<ggrid, 256>>>(xT, w_ih_l0, b_ih_l0, INPUT_DIM);
    gru_rec<<<2 * NCTAS_DIR, 256, SMEM_REC>>>(w_hh_l0, b_hh_l0, yA, out, 0);

    // layer 1
    gemm_xi<<<ggrid, 256>>>(yA, w_ih_lr, b_ih_lr, FEAT);
    gru_rec<<<2 * NCTAS_DIR, 256, SMEM_REC>>>(w_hh_lr, b_hh_lr, yB, out, 1);

    // layer 2
    gemm_xi<<<ggrid, 256>>>(yB, w_ih_lr + (size_t)2 * H3 * FEAT,
                            b_ih_lr + 2 * H3, FEAT);
    gru_rec<<<2 * NCTAS_DIR, 256, SMEM_REC>>>(w_hh_lr + (size_t)2 * H3 * H,
                                              b_hh_lr + 2 * H3, yA, out, 2);
}